// round 3
// baseline (speedup 1.0000x reference)
#include <cuda_runtime.h>
#include <cuda_fp16.h>
#include <cstdint>
#include <cstddef>

// ---------------------------------------------------------------------------
// Problem constants
// ---------------------------------------------------------------------------
static constexpr int MDIM = 8192;
static constexpr int NDIM = 4096;
static constexpr int KDIM = 4096;

static constexpr int BM = 128;
static constexpr int BN = 128;
static constexpr int BK = 64;                     // fp16 elems per stage (128B rows)
static constexpr int NSTAGES = KDIM / BK;         // 64 k-stages
static constexpr int PIPE = 3;                    // smem pipeline depth

static constexpr int TILE_BYTES = BM * 128;       // 16384 (one A or B stage)
static constexpr int SMEM_BYTES = 1024 + 2 * PIPE * TILE_BYTES;  // 99328

// ---------------------------------------------------------------------------
// Device scratch (allocation-free rule: __device__ globals)
// ---------------------------------------------------------------------------
__device__ __align__(256) __half g_xh[(size_t)MDIM * KDIM];   // 64 MB fp16 x
__device__ __align__(256) __half g_wh[(size_t)NDIM * KDIM];   // 32 MB fp16 ternary W
__device__ double g_partials[1024];
__device__ float  g_thresh;

// ---------------------------------------------------------------------------
// Helpers
// ---------------------------------------------------------------------------
__device__ __forceinline__ uint32_t smem_u32(const void* p) {
    uint32_t a;
    asm("{ .reg .u64 t; cvta.to.shared.u64 t, %1; cvt.u32.u64 %0, t; }"
        : "=r"(a) : "l"(p));
    return a;
}

__device__ __forceinline__ uint32_t swz(uint32_t off) {
    return off ^ ((off >> 3) & 0x70);   // SW128 within 1KB atom (8 rows x 128B)
}

__device__ __forceinline__ void cp16(uint32_t dst, const void* src) {
    asm volatile("cp.async.cg.shared.global [%0], [%1], 16;"
                 :: "r"(dst), "l"(src) : "memory");
}

__device__ __forceinline__ void ldm4(uint32_t& r0, uint32_t& r1,
                                     uint32_t& r2, uint32_t& r3, uint32_t addr) {
    asm volatile("ldmatrix.sync.aligned.m8n8.x4.shared.b16 {%0,%1,%2,%3}, [%4];"
                 : "=r"(r0), "=r"(r1), "=r"(r2), "=r"(r3) : "r"(addr));
}

__device__ __forceinline__ void mma16816(float* d, const uint32_t* a,
                                         const uint32_t* b) {
    asm volatile(
        "mma.sync.aligned.m16n8k16.row.col.f32.f16.f16.f32 "
        "{%0,%1,%2,%3}, {%4,%5,%6,%7}, {%8,%9}, {%0,%1,%2,%3};"
        : "+f"(d[0]), "+f"(d[1]), "+f"(d[2]), "+f"(d[3])
        : "r"(a[0]), "r"(a[1]), "r"(a[2]), "r"(a[3]), "r"(b[0]), "r"(b[1]));
}

// ---------------------------------------------------------------------------
// Kernel 1: deterministic |W| partial sums (double accumulation, fixed order)
// ---------------------------------------------------------------------------
__global__ void abssum_partial_kernel(const float* __restrict__ w, int n4) {
    __shared__ double sd[256];
    double s = 0.0;
    int stride = gridDim.x * blockDim.x;
    for (int i = blockIdx.x * blockDim.x + threadIdx.x; i < n4; i += stride) {
        float4 v = reinterpret_cast<const float4*>(w)[i];
        s += (double)(fabsf(v.x) + fabsf(v.y)) + (double)(fabsf(v.z) + fabsf(v.w));
    }
    sd[threadIdx.x] = s;
    __syncthreads();
    #pragma unroll
    for (int o = 128; o > 0; o >>= 1) {
        if (threadIdx.x < o) sd[threadIdx.x] += sd[threadIdx.x + o];
        __syncthreads();
    }
    if (threadIdx.x == 0) g_partials[blockIdx.x] = sd[0];
}

// Kernel 2: final reduce -> g_thresh = 0.5 * mean(|W|)
__global__ void abssum_final_kernel(int nblocks, double half_inv_n) {
    __shared__ double sd[1024];
    double s = (threadIdx.x < nblocks) ? g_partials[threadIdx.x] : 0.0;
    sd[threadIdx.x] = s;
    __syncthreads();
    #pragma unroll
    for (int o = 512; o > 0; o >>= 1) {
        if (threadIdx.x < o) sd[threadIdx.x] += sd[threadIdx.x + o];
        __syncthreads();
    }
    if (threadIdx.x == 0) g_thresh = (float)(sd[0] * half_inv_n);
}

// ---------------------------------------------------------------------------
// Kernel 3: ternary-quantize W -> fp16 {-1, 0, +1}
// ---------------------------------------------------------------------------
__device__ __forceinline__ __half qh(float v, float t) {
    float q = (v > t) ? 1.0f : ((v < -t) ? -1.0f : 0.0f);
    return __float2half_rn(q);
}

__global__ void quantw_kernel(const float* __restrict__ w, int n4) {
    float t = g_thresh;
    int stride = gridDim.x * blockDim.x;
    __half2* dst = reinterpret_cast<__half2*>(g_wh);
    for (int i = blockIdx.x * blockDim.x + threadIdx.x; i < n4; i += stride) {
        float4 v = reinterpret_cast<const float4*>(w)[i];
        dst[2 * i + 0] = __halves2half2(qh(v.x, t), qh(v.y, t));
        dst[2 * i + 1] = __halves2half2(qh(v.z, t), qh(v.w, t));
    }
}

// Kernel 4: X fp32 -> fp16
__global__ void cvtx_kernel(const float* __restrict__ x, int n4) {
    int stride = gridDim.x * blockDim.x;
    __half2* dst = reinterpret_cast<__half2*>(g_xh);
    for (int i = blockIdx.x * blockDim.x + threadIdx.x; i < n4; i += stride) {
        float4 v = reinterpret_cast<const float4*>(x)[i];
        dst[2 * i + 0] = __halves2half2(__float2half_rn(v.x), __float2half_rn(v.y));
        dst[2 * i + 1] = __halves2half2(__float2half_rn(v.z), __float2half_rn(v.w));
    }
}

// ---------------------------------------------------------------------------
// Kernel 5: fp16 mma.sync GEMM, 128x128 tile, cp.async 3-stage pipeline
//   8 warps in 2(m) x 4(n); warp tile 64x32; m16n8k16 fragments.
// ---------------------------------------------------------------------------
__global__ __launch_bounds__(256, 2) void ternary_gemm_kernel(
    const float* __restrict__ bias,
    const float* __restrict__ gamma_p,
    float* __restrict__ out) {
    extern __shared__ char smem_raw[];
    const uint32_t sb = smem_u32(smem_raw);
    const uint32_t base = (sb + 1023) & ~1023u;

    const int tid  = threadIdx.x;
    const int wid  = tid >> 5;
    const int lane = tid & 31;
    const int wm   = wid >> 2;        // 0..1
    const int wn   = wid & 3;         // 0..3
    const int m0   = blockIdx.y * BM;
    const int n0   = blockIdx.x * BN;

    const __half* gA = g_xh + (size_t)m0 * KDIM;
    const __half* gB = g_wh + (size_t)n0 * KDIM;

    // Per-thread cp.async mapping: 1024 16B-chunks per tile, 4 per thread
    const int l_row = tid >> 1;                      // not used; see loop below

    float acc[4][4][4];
    #pragma unroll
    for (int i = 0; i < 4; i++)
        #pragma unroll
        for (int j = 0; j < 4; j++)
            #pragma unroll
            for (int c = 0; c < 4; c++) acc[i][j][c] = 0.0f;

    auto load_stage = [&](int s, int buf) {
        const uint32_t sA = base + buf * TILE_BYTES;
        const uint32_t sB = base + PIPE * TILE_BYTES + buf * TILE_BYTES;
        const int k0 = s * BK;
        #pragma unroll
        for (int i = 0; i < 4; i++) {
            int idx = tid + i * 256;                 // 0..1023
            int row = idx >> 3;
            int c   = idx & 7;
            uint32_t off = swz((uint32_t)(row * 128 + c * 16));
            cp16(sA + off, gA + (size_t)row * KDIM + k0 + c * 8);
            cp16(sB + off, gB + (size_t)row * KDIM + k0 + c * 8);
        }
    };

    // Prologue: prefetch 2 stages
    load_stage(0, 0);
    asm volatile("cp.async.commit_group;" ::: "memory");
    load_stage(1, 1);
    asm volatile("cp.async.commit_group;" ::: "memory");

    const int frow  = lane & 15;        // fragment row within 16
    const int fcol8 = (lane >> 4) * 8;  // 8-half column group

    for (int s = 0; s < NSTAGES; s++) {
        asm volatile("cp.async.wait_group 1;" ::: "memory");
        __syncthreads();

        const int buf = s % PIPE;
        const uint32_t sA = base + buf * TILE_BYTES;
        const uint32_t sB = base + PIPE * TILE_BYTES + buf * TILE_BYTES;

        #pragma unroll
        for (int kk = 0; kk < 4; kk++) {
            uint32_t a[4][4];
            #pragma unroll
            for (int i = 0; i < 4; i++) {
                int row = wm * 64 + i * 16 + frow;
                uint32_t off = swz((uint32_t)(row * 128 + (kk * 16 + fcol8) * 2));
                ldm4(a[i][0], a[i][1], a[i][2], a[i][3], sA + off);
            }
            uint32_t b[4][2];
            #pragma unroll
            for (int jj = 0; jj < 2; jj++) {
                int row = wn * 32 + jj * 16 + frow;
                uint32_t off = swz((uint32_t)(row * 128 + (kk * 16 + fcol8) * 2));
                uint32_t t0, t1, t2, t3;
                ldm4(t0, t1, t2, t3, sB + off);
                b[2 * jj + 0][0] = t0; b[2 * jj + 0][1] = t2;   // n8 at jj*16+0
                b[2 * jj + 1][0] = t1; b[2 * jj + 1][1] = t3;   // n8 at jj*16+8
            }
            #pragma unroll
            for (int i = 0; i < 4; i++)
                #pragma unroll
                for (int j = 0; j < 4; j++)
                    mma16816(acc[i][j], a[i], b[j]);
        }

        if (s + 2 < NSTAGES) load_stage(s + 2, (s + 2) % PIPE);
        asm volatile("cp.async.commit_group;" ::: "memory");
    }

    // Epilogue: out = gamma * (acc + bias)
    const float gm = *gamma_p;
    #pragma unroll
    for (int i = 0; i < 4; i++) {
        const int mrow = m0 + wm * 64 + i * 16 + (lane >> 2);
        #pragma unroll
        for (int j = 0; j < 4; j++) {
            const int nc = n0 + wn * 32 + (j >> 1) * 16 + (j & 1) * 8 + (lane & 3) * 2;
            const float b0 = bias[nc], b1 = bias[nc + 1];
            float2 v0, v1;
            v0.x = gm * (acc[i][j][0] + b0);
            v0.y = gm * (acc[i][j][1] + b1);
            v1.x = gm * (acc[i][j][2] + b0);
            v1.y = gm * (acc[i][j][3] + b1);
            *reinterpret_cast<float2*>(out + (size_t)mrow * NDIM + nc)       = v0;
            *reinterpret_cast<float2*>(out + (size_t)(mrow + 8) * NDIM + nc) = v1;
        }
    }
    (void)l_row;
}

// ---------------------------------------------------------------------------
// kernel_launch
// ---------------------------------------------------------------------------
extern "C" void kernel_launch(void* const* d_in, const int* in_sizes, int n_in,
                              void* d_out, int out_size) {
    const float* x     = (const float*)d_in[0];   // [8192, 4096]
    const float* w     = (const float*)d_in[1];   // [4096, 4096]
    const float* bias  = (const float*)d_in[2];   // [4096]
    const float* gamma = (const float*)d_in[3];   // scalar
    float* out = (float*)d_out;                   // [8192, 4096]

    const int nW = NDIM * KDIM;                   // 16,777,216
    const int nX = MDIM * KDIM;                   // 33,554,432

    abssum_partial_kernel<<<1024, 256>>>(w, nW / 4);
    abssum_final_kernel<<<1, 1024>>>(1024, 0.5 / (double)nW);
    quantw_kernel<<<2048, 256>>>(w, nW / 4);
    cvtx_kernel<<<4096, 256>>>(x, nX / 4);

    cudaFuncSetAttribute(ternary_gemm_kernel,
                         cudaFuncAttributeMaxDynamicSharedMemorySize, SMEM_BYTES);
    dim3 grid(NDIM / BN, MDIM / BM);              // (32, 64)
    ternary_gemm_kernel<<<grid, 256, SMEM_BYTES>>>(bias, gamma, out);
}